// round 12
// baseline (speedup 1.0000x reference)
#include <cuda_runtime.h>
#include <cstdint>

// Problem shape (fixed by the dataset)
#define NLAYERS 60
#define NB 2048
#define NC 128
#define NCOLS (NB * NC)   // 262144 columns

// Exact-op intrinsics: nvcc/ptxas will neither fuse nor split these.
// DO NOT TOUCH — this sequence replicates XLA/LLVM contraction bit-exactly
// (R4: rel_err 1.4e-8). The recursion is chaotic; any change diverges.
#define FMUL(a,b)    __fmul_rn((a),(b))
#define FADD(a,b)    __fadd_rn((a),(b))
#define FSUB(a,b)    __fsub_rn((a),(b))
#define FMA(a,b,c)   __fmaf_rn((a),(b),(c))

struct In8 {
    float t_d, t_df;
    float etd, erd, ead;     // e_split_direct[...,0..2]
    float etf, erf, eaf;     // e_split_diffuse[...,0..2]
};

// Streaming loads: every input byte is read exactly once -> evict-first.
__device__ __forceinline__ void load_layer(
    const float* __restrict__ t_direct,
    const float* __restrict__ t_diffuse,
    const float* __restrict__ es_d,
    const float* __restrict__ es_df,
    int l, int i, In8& v)
{
    size_t off  = (size_t)l * NCOLS + i;
    v.t_d  = __ldcs(t_direct  + off);
    v.t_df = __ldcs(t_diffuse + off);
    const float* pd = es_d  + off * 3;
    const float* pf = es_df + off * 3;
    v.etd = __ldcs(pd + 0);
    v.erd = __ldcs(pd + 1);
    v.ead = __ldcs(pd + 2);
    v.etf = __ldcs(pf + 0);
    v.erf = __ldcs(pf + 1);
    v.eaf = __ldcs(pf + 2);
}

// R5's memory engine (explicit double-buffer prefetch, 48-reg budget,
// 40 warps/SM) with 128-thread CTAs: 10 CTAs/SM -> same warp budget and reg
// cap as (256,5), but finer CTA granularity packs the second wave evenly.
__global__ void __launch_bounds__(128, 10)
upward_prop_kernel(
    const float* __restrict__ t_direct,
    const float* __restrict__ t_diffuse,
    const float* __restrict__ es_d,
    const float* __restrict__ es_df,
    const float* __restrict__ r_bottom_direct,
    const float* __restrict__ r_bottom_diffuse,
    const float* __restrict__ a_bottom_direct,
    const float* __restrict__ a_bottom_diffuse,
    float* __restrict__ out)  // (L, B, C, 8)
{
    int i = blockIdx.x * blockDim.x + threadIdx.x;
    if (i >= NCOLS) return;

    // scan state
    float r_b_d  = __ldcs(r_bottom_direct  + i);
    float r_b_df = __ldcs(r_bottom_diffuse + i);
    float a_b_d  = __ldcs(a_bottom_direct  + i);
    float a_b_df = __ldcs(a_bottom_diffuse + i);

    In8 cur, nxt;
    load_layer(t_direct, t_diffuse, es_d, es_df, 0, i, cur);

    for (int l = 0; l < NLAYERS; ++l) {
        // prefetch next layer's inputs (8 loads in flight over this layer's math)
        if (l + 1 < NLAYERS)
            load_layer(t_direct, t_diffuse, es_d, es_df, l + 1, i, nxt);

        const float t_d  = cur.t_d,  t_df = cur.t_df;
        const float e_t_d = cur.etd, e_r_d = cur.erd, e_a_d = cur.ead;
        const float e_t_df = cur.etf, e_r_df = cur.erf, e_a_df = cur.eaf;

        // ===== XLA/LLVM-contracted replica (HLO CSE + DAGCombiner FMA rules) =====
        const float e_d  = FSUB(1.0f, t_d);
        const float e_df = FSUB(1.0f, t_df);

        const float m1  = FMUL(e_df, e_r_df);
        const float m3  = FMUL(t_d,  r_b_d);
        const float m7  = FMUL(e_d,  e_t_d);
        const float m18 = FMUL(e_df, e_t_df);
        const float m20 = FMUL(t_df, r_b_df);

        const float denom = FMA(-m1, r_b_df, 1.0f);
        const float d = __frcp_rn(denom);

        const float s = FADD(t_df, m18);

        // ---- direct ----
        const float m4  = FMUL(m3, e_df);
        const float m5  = FMUL(m4, e_r_df);
        const float t_m_d = FMA(m5, d, FMUL(m7, d));

        const float a_bm_d = FMA(t_d, a_b_d, FMUL(t_m_d, a_b_df));

        const float m12 = FMUL(m7, r_b_df);
        const float r_bm_d = FMA(m3, d, FMUL(m12, d));

        const float m15 = FMUL(r_bm_d, e_df);
        const float a_tm_d = FMA(e_d, e_a_d, FMUL(m15, e_a_df));

        const float r_m_d = FMA(e_d, e_r_d, FMUL(r_bm_d, s));

        // ---- diffuse ----
        const float m21 = FMUL(m20, e_df);
        const float m22 = FMUL(m21, e_r_df);
        const float t_m_df = FMA(m22, d, FMUL(m18, d));

        const float a_bm_df = FMA(t_df, a_b_df, FMUL(t_m_df, a_b_df));

        const float m28 = FMUL(m18, r_b_df);
        const float r_bm_df = FMA(m20, d, FMUL(m28, d));

        const float m31 = FMUL(r_bm_df, e_df);
        const float a_tm_df = FMA(e_df, e_a_df, FMUL(m31, e_a_df));

        const float r_m_df = FMA(r_bm_df, s, m1);

        // output: [t_m_d, t_m_df, r_bm_d, r_bm_df, a_tm_d, a_tm_df, a_bm_d, a_bm_df]
        float4* o = reinterpret_cast<float4*>(out + ((size_t)l * NCOLS + i) * 8);
        __stcs(o + 0, make_float4(t_m_d,  t_m_df,  r_bm_d,  r_bm_df));
        __stcs(o + 1, make_float4(a_tm_d, a_tm_df, a_bm_d,  a_bm_df));

        // next state = (r_multi_d, r_multi_df, a_top_multi_d, a_top_multi_df)
        r_b_d  = r_m_d;
        r_b_df = r_m_df;
        a_b_d  = a_tm_d;
        a_b_df = a_tm_df;

        cur = nxt;
    }
}

extern "C" void kernel_launch(void* const* d_in, const int* in_sizes, int n_in,
                              void* d_out, int out_size)
{
    const float* t_direct   = (const float*)d_in[0];
    const float* t_diffuse  = (const float*)d_in[1];
    const float* es_d       = (const float*)d_in[2];
    const float* es_df      = (const float*)d_in[3];
    const float* r_b_d      = (const float*)d_in[4];
    const float* r_b_df     = (const float*)d_in[5];
    const float* a_b_d      = (const float*)d_in[6];
    const float* a_b_df     = (const float*)d_in[7];
    float* out = (float*)d_out;

    dim3 block(128);
    dim3 grid((NCOLS + 127) / 128);
    upward_prop_kernel<<<grid, block>>>(t_direct, t_diffuse, es_d, es_df,
                                        r_b_d, r_b_df, a_b_d, a_b_df, out);
}

// round 13
// speedup vs baseline: 1.0670x; 1.0670x over previous
#include <cuda_runtime.h>
#include <cstdint>

// Problem shape (fixed by the dataset)
#define NLAYERS 60
#define NB 2048
#define NC 128
#define NCOLS (NB * NC)     // 262144 columns
#define COLS_PER_THREAD 2
#define NTHREADS (NCOLS / COLS_PER_THREAD)   // 131072
#define CSTRIDE NTHREADS                     // column stride between reps

// Exact-op intrinsics: nvcc/ptxas will neither fuse nor split these.
// DO NOT TOUCH — this sequence replicates XLA/LLVM contraction bit-exactly
// (R4: rel_err 1.4e-8). The recursion is chaotic; any change diverges.
#define FMUL(a,b)    __fmul_rn((a),(b))
#define FADD(a,b)    __fadd_rn((a),(b))
#define FSUB(a,b)    __fsub_rn((a),(b))
#define FMA(a,b,c)   __fmaf_rn((a),(b),(c))

struct In8 {
    float t_d, t_df;
    float etd, erd, ead;     // e_split_direct[...,0..2]
    float etf, erf, eaf;     // e_split_diffuse[...,0..2]
};

// Streaming loads: every input byte is read exactly once -> evict-first.
__device__ __forceinline__ void load_layer(
    const float* __restrict__ t_direct,
    const float* __restrict__ t_diffuse,
    const float* __restrict__ es_d,
    const float* __restrict__ es_df,
    int l, int i, In8& v)
{
    size_t off  = (size_t)l * NCOLS + i;
    v.t_d  = __ldcs(t_direct  + off);
    v.t_df = __ldcs(t_diffuse + off);
    const float* pd = es_d  + off * 3;
    const float* pf = es_df + off * 3;
    v.etd = __ldcs(pd + 0);
    v.erd = __ldcs(pd + 1);
    v.ead = __ldcs(pd + 2);
    v.etf = __ldcs(pf + 0);
    v.erf = __ldcs(pf + 1);
    v.eaf = __ldcs(pf + 2);
}

// Full 60-layer scan of one column. Same register footprint each call.
__device__ __forceinline__ void scan_column(
    const float* __restrict__ t_direct,
    const float* __restrict__ t_diffuse,
    const float* __restrict__ es_d,
    const float* __restrict__ es_df,
    const float* __restrict__ r_bottom_direct,
    const float* __restrict__ r_bottom_diffuse,
    const float* __restrict__ a_bottom_direct,
    const float* __restrict__ a_bottom_diffuse,
    float* __restrict__ out, int i)
{
    float r_b_d  = __ldcs(r_bottom_direct  + i);
    float r_b_df = __ldcs(r_bottom_diffuse + i);
    float a_b_d  = __ldcs(a_bottom_direct  + i);
    float a_b_df = __ldcs(a_bottom_diffuse + i);

    In8 cur, nxt;
    load_layer(t_direct, t_diffuse, es_d, es_df, 0, i, cur);

    for (int l = 0; l < NLAYERS; ++l) {
        // prefetch next layer's inputs (8 loads in flight over this layer's math)
        if (l + 1 < NLAYERS)
            load_layer(t_direct, t_diffuse, es_d, es_df, l + 1, i, nxt);

        const float t_d  = cur.t_d,  t_df = cur.t_df;
        const float e_t_d = cur.etd, e_r_d = cur.erd, e_a_d = cur.ead;
        const float e_t_df = cur.etf, e_r_df = cur.erf, e_a_df = cur.eaf;

        // ===== XLA/LLVM-contracted replica (HLO CSE + DAGCombiner FMA rules) =====
        const float e_d  = FSUB(1.0f, t_d);
        const float e_df = FSUB(1.0f, t_df);

        const float m1  = FMUL(e_df, e_r_df);
        const float m3  = FMUL(t_d,  r_b_d);
        const float m7  = FMUL(e_d,  e_t_d);
        const float m18 = FMUL(e_df, e_t_df);
        const float m20 = FMUL(t_df, r_b_df);

        const float denom = FMA(-m1, r_b_df, 1.0f);
        const float d = __frcp_rn(denom);

        const float s = FADD(t_df, m18);

        // ---- direct ----
        const float m4  = FMUL(m3, e_df);
        const float m5  = FMUL(m4, e_r_df);
        const float t_m_d = FMA(m5, d, FMUL(m7, d));

        const float a_bm_d = FMA(t_d, a_b_d, FMUL(t_m_d, a_b_df));

        const float m12 = FMUL(m7, r_b_df);
        const float r_bm_d = FMA(m3, d, FMUL(m12, d));

        const float m15 = FMUL(r_bm_d, e_df);
        const float a_tm_d = FMA(e_d, e_a_d, FMUL(m15, e_a_df));

        const float r_m_d = FMA(e_d, e_r_d, FMUL(r_bm_d, s));

        // ---- diffuse ----
        const float m21 = FMUL(m20, e_df);
        const float m22 = FMUL(m21, e_r_df);
        const float t_m_df = FMA(m22, d, FMUL(m18, d));

        const float a_bm_df = FMA(t_df, a_b_df, FMUL(t_m_df, a_b_df));

        const float m28 = FMUL(m18, r_b_df);
        const float r_bm_df = FMA(m20, d, FMUL(m28, d));

        const float m31 = FMUL(r_bm_df, e_df);
        const float a_tm_df = FMA(e_df, e_a_df, FMUL(m31, e_a_df));

        const float r_m_df = FMA(r_bm_df, s, m1);

        // output: [t_m_d, t_m_df, r_bm_d, r_bm_df, a_tm_d, a_tm_df, a_bm_d, a_bm_df]
        float4* o = reinterpret_cast<float4*>(out + ((size_t)l * NCOLS + i) * 8);
        __stcs(o + 0, make_float4(t_m_d,  t_m_df,  r_bm_d,  r_bm_df));
        __stcs(o + 1, make_float4(a_tm_d, a_tm_df, a_bm_d,  a_bm_df));

        // next state
        r_b_d  = r_m_d;
        r_b_df = r_m_df;
        a_b_d  = a_tm_d;
        a_b_df = a_tm_df;

        cur = nxt;
    }
}

// 1024 CTAs x 128 thr = 131072 threads; each does exactly 2 columns
// sequentially -> one perfectly balanced wave, no 38%-full tail wave.
// 10 CTAs/SM cap keeps the 48-reg budget of the best (R5/R12) loop body.
__global__ void __launch_bounds__(128, 10)
upward_prop_kernel(
    const float* __restrict__ t_direct,
    const float* __restrict__ t_diffuse,
    const float* __restrict__ es_d,
    const float* __restrict__ es_df,
    const float* __restrict__ r_bottom_direct,
    const float* __restrict__ r_bottom_diffuse,
    const float* __restrict__ a_bottom_direct,
    const float* __restrict__ a_bottom_diffuse,
    float* __restrict__ out)  // (L, B, C, 8)
{
    int i = blockIdx.x * blockDim.x + threadIdx.x;
    if (i >= NTHREADS) return;

    scan_column(t_direct, t_diffuse, es_d, es_df,
                r_bottom_direct, r_bottom_diffuse,
                a_bottom_direct, a_bottom_diffuse, out, i);
    scan_column(t_direct, t_diffuse, es_d, es_df,
                r_bottom_direct, r_bottom_diffuse,
                a_bottom_direct, a_bottom_diffuse, out, i + CSTRIDE);
}

extern "C" void kernel_launch(void* const* d_in, const int* in_sizes, int n_in,
                              void* d_out, int out_size)
{
    const float* t_direct   = (const float*)d_in[0];
    const float* t_diffuse  = (const float*)d_in[1];
    const float* es_d       = (const float*)d_in[2];
    const float* es_df      = (const float*)d_in[3];
    const float* r_b_d      = (const float*)d_in[4];
    const float* r_b_df     = (const float*)d_in[5];
    const float* a_b_d      = (const float*)d_in[6];
    const float* a_b_df     = (const float*)d_in[7];
    float* out = (float*)d_out;

    dim3 block(128);
    dim3 grid(NTHREADS / 128);   // 1024 CTAs, single balanced wave
    upward_prop_kernel<<<grid, block>>>(t_direct, t_diffuse, es_d, es_df,
                                        r_b_d, r_b_df, a_b_d, a_b_df, out);
}